// round 8
// baseline (speedup 1.0000x reference)
#include <cuda_runtime.h>
#include <cuda_fp16.h>

#define N_NODES  50000
#define N_EDGES  1600000
#define N_GRAPHS 1000

// ---------------- scratch (device globals; no allocation allowed) ----------
__device__ __align__(16) float  g_x8[N_NODES * 8];      // padded node features
__device__ __align__(16) float  g_aggr1[N_NODES * 8];   // layer1 aggregation
__device__ __align__(16) float  g_h1[N_NODES * 64];     // layer1 output (fp32)
__device__ __align__(16) __half g_h1h[N_NODES * 64];    // layer1 output (fp16 gather copy)
__device__ __align__(16) float  g_aggr2[N_NODES * 64];  // layer2 aggregation
__device__ __align__(16) float  g_sums[N_GRAPHS * 64];  // pooled sums
__device__ __align__(16) float  g_cnt[N_GRAPHS];        // per-graph node counts
// binning structures (rebuilt every launch; deterministic set, order-free sum)
__device__ __align__(16) int    g_deg[N_NODES];         // per-dst degree histogram
__device__ __align__(16) int    g_off[N_NODES + 4];     // segment offsets (exclusive scan)
__device__ __align__(16) int    g_cur[N_NODES];         // running fill cursor
__device__ __align__(16) int2   g_erec[N_EDGES];        // dst-sorted records (src, edge_id)

// ---------------- zero scratch + pad x ---------------------------------------
// float4 slots: aggr1 100000 | deg 12500 (int4) | sums 16000  => 128500
#define Z_AGGR1 (N_NODES * 2)
#define Z_DEG   (Z_AGGR1 + N_NODES / 4)
#define Z_END   (Z_DEG + N_GRAPHS * 16)
__global__ void zero_kernel(const float* __restrict__ x) {
    int i = blockIdx.x * blockDim.x + threadIdx.x;
    if (i < Z_AGGR1) {
        reinterpret_cast<float4*>(g_aggr1)[i] = make_float4(0.f, 0.f, 0.f, 0.f);
        int node = i >> 1, h = i & 1;
        int base = node * 7 + h * 4;
        float4 v;
        v.x = __ldg(&x[base + 0]);
        v.y = __ldg(&x[base + 1]);
        v.z = __ldg(&x[base + 2]);
        v.w = (h == 0) ? __ldg(&x[base + 3]) : 0.f;   // j=7 pad
        reinterpret_cast<float4*>(g_x8)[i] = v;
    } else if (i < Z_DEG) {
        reinterpret_cast<int4*>(g_deg)[i - Z_AGGR1] = make_int4(0, 0, 0, 0);
    } else if (i < Z_END) {
        reinterpret_cast<float4*>(g_sums)[i - Z_DEG] = make_float4(0.f, 0.f, 0.f, 0.f);
    }
    if (i < N_GRAPHS) g_cnt[i] = 0.f;
}

// ---------------- binning pass 1: histogram of dst ---------------------------
__global__ void hist_kernel(const int* __restrict__ ei) {
    int e = blockIdx.x * blockDim.x + threadIdx.x;
    if (e >= N_EDGES) return;
    atomicAdd(&g_deg[__ldg(&ei[N_EDGES + e])], 1);
}

// ---------------- binning pass 2: exclusive scan (one block) -----------------
#define SCAN_T 1024
#define CHUNK  ((N_NODES + SCAN_T - 1) / SCAN_T)   // 49
__global__ void scan_kernel() {
    __shared__ int ssum[SCAN_T];
    int t = threadIdx.x;
    int beg = t * CHUNK;
    int end = min(beg + CHUNK, N_NODES);
    int s = 0;
    for (int i = beg; i < end; i++) s += g_deg[i];
    ssum[t] = s;
    __syncthreads();
    for (int d = 1; d < SCAN_T; d <<= 1) {
        int v = (t >= d) ? ssum[t - d] : 0;
        __syncthreads();
        ssum[t] += v;
        __syncthreads();
    }
    int run = (t > 0) ? ssum[t - 1] : 0;   // exclusive base
    for (int i = beg; i < end; i++) {
        int dg = g_deg[i];
        g_off[i] = run;
        g_cur[i] = run;
        run += dg;
    }
    if (t == 0) g_off[N_NODES] = N_EDGES;
}

// ---------------- binning pass 3: scatter edge records by dst ----------------
__global__ void scatter_kernel(const int* __restrict__ ei) {
    int e = blockIdx.x * blockDim.x + threadIdx.x;
    if (e >= N_EDGES) return;
    int src = __ldg(&ei[e]);
    int dst = __ldg(&ei[N_EDGES + e]);
    int pos = atomicAdd(&g_cur[dst], 1);
    g_erec[pos] = make_int2(src, e);
}

// ---------------- layer 1 edge pass (d = 7), grid-stride, register weights --
__global__ void edge1_kernel(const float* __restrict__ ea,
                             const int*   __restrict__ ei,
                             const float* __restrict__ We1,
                             const float* __restrict__ be1) {
    float w[4][7], b[7];
#pragma unroll
    for (int i = 0; i < 4; i++)
#pragma unroll
        for (int j = 0; j < 7; j++)
            w[i][j] = __ldg(&We1[i * 7 + j]);
#pragma unroll
    for (int j = 0; j < 7; j++) b[j] = __ldg(&be1[j]);

    int t  = blockIdx.x * blockDim.x + threadIdx.x;
    int nt = gridDim.x * blockDim.x;
    for (int e = t; e < N_EDGES; e += nt) {
        int src = __ldg(&ei[e]);
        int dst = __ldg(&ei[N_EDGES + e]);
        float4 a  = __ldg(reinterpret_cast<const float4*>(ea) + e);
        float4 x0 = __ldg(reinterpret_cast<const float4*>(g_x8) + src * 2);
        float4 x1 = __ldg(reinterpret_cast<const float4*>(g_x8) + src * 2 + 1);
        float xs[8] = {x0.x, x0.y, x0.z, x0.w, x1.x, x1.y, x1.z, 0.f};
        float v[8];
#pragma unroll
        for (int j = 0; j < 7; j++) {
            float m = b[j] + a.x * w[0][j] + a.y * w[1][j]
                            + a.z * w[2][j] + a.w * w[3][j];
            v[j] = fmaxf(m + xs[j], 0.f);
        }
        v[7] = 0.f;
        float* p = g_aggr1 + dst * 8;
        asm volatile("red.global.add.v4.f32 [%0], {%1, %2, %3, %4};"
                     :: "l"(p), "f"(v[0]), "f"(v[1]), "f"(v[2]), "f"(v[3]) : "memory");
        asm volatile("red.global.add.v4.f32 [%0], {%1, %2, %3, %4};"
                     :: "l"(p + 4), "f"(v[4]), "f"(v[5]), "f"(v[6]), "f"(v[7]) : "memory");
    }
}

// ---------------- layer 1 node MLP: 7 -> 64 -> 64, 4-node blocked ----------
#define N_GROUPS (N_NODES / 4)
__global__ void node1_kernel(const float* __restrict__ W1a,
                             const float* __restrict__ b1a,
                             const float* __restrict__ W1b,
                             const float* __restrict__ b1b) {
    __shared__ float2 sWa[7 * 32];
    __shared__ float2 sWb[64 * 32];
    __shared__ float  sba[64];
    __shared__ float  sbb[64];
    for (int i = threadIdx.x; i < 7 * 32; i += blockDim.x)
        sWa[i] = reinterpret_cast<const float2*>(W1a)[i];
    for (int i = threadIdx.x; i < 64 * 32; i += blockDim.x)
        sWb[i] = reinterpret_cast<const float2*>(W1b)[i];
    if (threadIdx.x < 64) { sba[threadIdx.x] = b1a[threadIdx.x]; sbb[threadIdx.x] = b1b[threadIdx.x]; }
    __syncthreads();

    int warp = (blockIdx.x * blockDim.x + threadIdx.x) >> 5;
    int nw   = (gridDim.x * blockDim.x) >> 5;
    int lane = threadIdx.x & 31;
    int j    = lane * 2;

    for (int grp = warp; grp < N_GROUPS; grp += nw) {
        int n0 = grp * 4;
        float z[4][7];
#pragma unroll
        for (int m = 0; m < 4; m++)
#pragma unroll
            for (int k = 0; k < 7; k++)
                z[m][k] = g_x8[(n0 + m) * 8 + k] + g_aggr1[(n0 + m) * 8 + k];

        float t0[4], t1[4];
#pragma unroll
        for (int m = 0; m < 4; m++) { t0[m] = sba[j]; t1[m] = sba[j + 1]; }
#pragma unroll
        for (int k = 0; k < 7; k++) {
            float2 w = sWa[k * 32 + lane];
#pragma unroll
            for (int m = 0; m < 4; m++) {
                t0[m] += z[m][k] * w.x;
                t1[m] += z[m][k] * w.y;
            }
        }
#pragma unroll
        for (int m = 0; m < 4; m++) { t0[m] = fmaxf(t0[m], 0.f); t1[m] = fmaxf(t1[m], 0.f); }

        float a0[4], a1[4];
#pragma unroll
        for (int m = 0; m < 4; m++) { a0[m] = sbb[j]; a1[m] = sbb[j + 1]; }
#pragma unroll
        for (int k = 0; k < 64; k++) {
            float2 w = sWb[k * 32 + lane];
#pragma unroll
            for (int m = 0; m < 4; m++) {
                float tk = __shfl_sync(0xffffffffu, (k & 1) ? t1[m] : t0[m], k >> 1);
                a0[m] += tk * w.x;
                a1[m] += tk * w.y;
            }
        }
#pragma unroll
        for (int m = 0; m < 4; m++) {
            float v0 = fmaxf(a0[m], 0.f);   // outer relu from reference
            float v1 = fmaxf(a1[m], 0.f);
            *reinterpret_cast<float2*>(g_h1 + (n0 + m) * 64 + j) = make_float2(v0, v1);
            *reinterpret_cast<__half2*>(g_h1h + (n0 + m) * 64 + j) =
                __floats2half2_rn(v0, v1);
        }
    }
}

// ---------------- layer 2 edge pass: half-warp per DST node ------------------
// walks the dst-sorted segment, accumulates 64-wide sum in registers,
// writes aggr2[dst] with a single plain store. NO atomics.
__global__ void __launch_bounds__(256)
edge2_kernel(const float* __restrict__ ea,
             const float* __restrict__ We2,
             const float* __restrict__ be2) {
    int l   = threadIdx.x & 15;                        // output slice 4l..4l+3
    int dst = (blockIdx.x * blockDim.x + threadIdx.x) >> 4;
    if (dst >= N_NODES) return;

    float4 t0 = __ldg(reinterpret_cast<const float4*>(We2 + 0 * 64) + l);
    float4 t1 = __ldg(reinterpret_cast<const float4*>(We2 + 1 * 64) + l);
    float4 t2 = __ldg(reinterpret_cast<const float4*>(We2 + 2 * 64) + l);
    float4 t3 = __ldg(reinterpret_cast<const float4*>(We2 + 3 * 64) + l);
    float4 bb = __ldg(reinterpret_cast<const float4*>(be2) + l);

    int beg = __ldg(&g_off[dst]);
    int end = __ldg(&g_off[dst + 1]);

    float4 acc = make_float4(0.f, 0.f, 0.f, 0.f);
    int2 rec = (beg < end) ? __ldg(&g_erec[beg]) : make_int2(0, 0);
    for (int i = beg; i < end; i++) {
        // loads for current edge (rec already in flight)
        float4 a  = __ldg(reinterpret_cast<const float4*>(ea) + rec.y);
        uint2  hr = __ldg(reinterpret_cast<const uint2*>(g_h1h + rec.x * 64) + l);
        // prefetch next record while current gather is outstanding
        if (i + 1 < end) rec = __ldg(&g_erec[i + 1]);

        float2 h0 = __half22float2(*reinterpret_cast<__half2*>(&hr.x));
        float2 h1 = __half22float2(*reinterpret_cast<__half2*>(&hr.y));
        acc.x += fmaxf(bb.x + a.x*t0.x + a.y*t1.x + a.z*t2.x + a.w*t3.x + h0.x, 0.f);
        acc.y += fmaxf(bb.y + a.x*t0.y + a.y*t1.y + a.z*t2.y + a.w*t3.y + h0.y, 0.f);
        acc.z += fmaxf(bb.z + a.x*t0.z + a.y*t1.z + a.z*t2.z + a.w*t3.z + h1.x, 0.f);
        acc.w += fmaxf(bb.w + a.x*t0.w + a.y*t1.w + a.z*t2.w + a.w*t3.w + h1.y, 0.f);
    }
    reinterpret_cast<float4*>(g_aggr2 + dst * 64)[l] = acc;   // plain store
}

// ---------------- layer 2 node MLP (64->64->64) + pool, 4-node blocked -----
__global__ void node2pool_kernel(const int*   __restrict__ batch,
                                 const float* __restrict__ W2a,
                                 const float* __restrict__ b2a,
                                 const float* __restrict__ W2b,
                                 const float* __restrict__ b2b) {
    __shared__ float2 sWa[64 * 32];
    __shared__ float2 sWb[64 * 32];
    __shared__ float  sba[64];
    __shared__ float  sbb[64];
    for (int i = threadIdx.x; i < 64 * 32; i += blockDim.x) {
        sWa[i] = reinterpret_cast<const float2*>(W2a)[i];
        sWb[i] = reinterpret_cast<const float2*>(W2b)[i];
    }
    if (threadIdx.x < 64) { sba[threadIdx.x] = b2a[threadIdx.x]; sbb[threadIdx.x] = b2b[threadIdx.x]; }
    __syncthreads();

    int warp = (blockIdx.x * blockDim.x + threadIdx.x) >> 5;
    int nw   = (gridDim.x * blockDim.x) >> 5;
    int lane = threadIdx.x & 31;
    int j    = lane * 2;

    for (int grp = warp; grp < N_GROUPS; grp += nw) {
        int n0 = grp * 4;
        float z0[4], z1[4];
#pragma unroll
        for (int m = 0; m < 4; m++) {
            float2 hv = *reinterpret_cast<const float2*>(g_h1 + (n0 + m) * 64 + j);
            float2 av = *reinterpret_cast<const float2*>(g_aggr2 + (n0 + m) * 64 + j);
            z0[m] = hv.x + av.x;
            z1[m] = hv.y + av.y;
        }

        float t0[4], t1[4];
#pragma unroll
        for (int m = 0; m < 4; m++) { t0[m] = sba[j]; t1[m] = sba[j + 1]; }
#pragma unroll
        for (int k = 0; k < 64; k++) {
            float2 w = sWa[k * 32 + lane];
#pragma unroll
            for (int m = 0; m < 4; m++) {
                float zk = __shfl_sync(0xffffffffu, (k & 1) ? z1[m] : z0[m], k >> 1);
                t0[m] += zk * w.x;
                t1[m] += zk * w.y;
            }
        }
#pragma unroll
        for (int m = 0; m < 4; m++) { t0[m] = fmaxf(t0[m], 0.f); t1[m] = fmaxf(t1[m], 0.f); }

        float a0[4], a1[4];
#pragma unroll
        for (int m = 0; m < 4; m++) { a0[m] = sbb[j]; a1[m] = sbb[j + 1]; }
#pragma unroll
        for (int k = 0; k < 64; k++) {
            float2 w = sWb[k * 32 + lane];
#pragma unroll
            for (int m = 0; m < 4; m++) {
                float tk = __shfl_sync(0xffffffffu, (k & 1) ? t1[m] : t0[m], k >> 1);
                a0[m] += tk * w.x;
                a1[m] += tk * w.y;
            }
        }
#pragma unroll
        for (int m = 0; m < 4; m++) {
            float v0 = fmaxf(a0[m], 0.f);   // outer relu from reference
            float v1 = fmaxf(a1[m], 0.f);
            int g = batch[n0 + m];
            float* p = g_sums + g * 64 + j;
            asm volatile("red.global.add.v2.f32 [%0], {%1, %2};"
                         :: "l"(p), "f"(v0), "f"(v1) : "memory");
            if (lane == 0) atomicAdd(&g_cnt[g], 1.0f);
        }
    }
}

// ---------------- final FC: pooled[G,64] @ Wfc[64,12] + bfc -----------------
__global__ void fc_kernel(const float* __restrict__ Wfc,
                          const float* __restrict__ bfc,
                          float* __restrict__ out) {
    int i = blockIdx.x * blockDim.x + threadIdx.x;
    if (i >= N_GRAPHS * 12) return;
    int g = i / 12;
    int c = i % 12;
    float inv = 1.0f / fmaxf(g_cnt[g], 1.0f);
    float acc = 0.f;
#pragma unroll
    for (int k = 0; k < 64; k++)
        acc += g_sums[g * 64 + k] * Wfc[k * 12 + c];
    out[i] = bfc[c] + inv * acc;
}

// ---------------- launch ----------------------------------------------------
extern "C" void kernel_launch(void* const* d_in, const int* in_sizes, int n_in,
                              void* d_out, int out_size) {
    const float* x    = (const float*)d_in[0];
    const float* ea   = (const float*)d_in[1];
    const int*   ei   = (const int*)  d_in[2];
    const int*   batch= (const int*)  d_in[3];
    const float* We1  = (const float*)d_in[4];
    const float* be1  = (const float*)d_in[5];
    const float* W1a  = (const float*)d_in[6];
    const float* b1a  = (const float*)d_in[7];
    const float* W1b  = (const float*)d_in[8];
    const float* b1b  = (const float*)d_in[9];
    const float* We2  = (const float*)d_in[10];
    const float* be2  = (const float*)d_in[11];
    const float* W2a  = (const float*)d_in[12];
    const float* b2a  = (const float*)d_in[13];
    const float* W2b  = (const float*)d_in[14];
    const float* b2b  = (const float*)d_in[15];
    const float* Wfc  = (const float*)d_in[16];
    const float* bfc  = (const float*)d_in[17];
    float* out = (float*)d_out;

    zero_kernel<<<(Z_END + 255) / 256, 256>>>(x);
    hist_kernel<<<(N_EDGES + 255) / 256, 256>>>(ei);
    scan_kernel<<<1, SCAN_T>>>();
    scatter_kernel<<<(N_EDGES + 255) / 256, 256>>>(ei);
    edge1_kernel<<<1184, 256>>>(ea, ei, We1, be1);
    node1_kernel<<<592, 256>>>(W1a, b1a, W1b, b1b);
    edge2_kernel<<<(N_NODES * 16 + 255) / 256, 256>>>(ea, We2, be2);
    node2pool_kernel<<<592, 256>>>(batch, W2a, b2a, W2b, b2b);
    fc_kernel<<<(N_GRAPHS * 12 + 255) / 256, 256>>>(Wfc, bfc, out);
}

// round 9
// speedup vs baseline: 1.0129x; 1.0129x over previous
#include <cuda_runtime.h>
#include <cuda_fp16.h>

#define N_NODES  50000
#define N_EDGES  1600000
#define N_GRAPHS 1000

// ---------------- scratch (device globals; no allocation allowed) ----------
__device__ __align__(16) float  g_x8[N_NODES * 8];      // padded node features (fp32)
__device__ __align__(16) __half g_x8h[N_NODES * 8];     // padded node features (fp16)
__device__ __align__(16) float  g_aggr1[N_NODES * 8];   // layer1 aggregation
__device__ __align__(16) float  g_h1[N_NODES * 64];     // layer1 output (fp32)
__device__ __align__(16) __half g_h1h[N_NODES * 64];    // layer1 output (fp16 gather copy)
__device__ __align__(16) float  g_aggr2[N_NODES * 64];  // layer2 aggregation
__device__ __align__(16) float  g_sums[N_GRAPHS * 64];  // pooled sums
__device__ __align__(16) float  g_cnt[N_GRAPHS];        // per-graph node counts
// binning structures (rebuilt every launch)
__device__ __align__(16) int    g_deg[N_NODES];         // per-dst degree histogram
__device__ __align__(16) int    g_off[N_NODES + 4];     // segment offsets
__device__ __align__(16) int    g_cur[N_NODES];         // fill cursors
__device__ __align__(16) int4   g_erec[N_EDGES];        // dst-sorted records (src, eid, dst, 0)

// ---------------- zero scratch + pad x ---------------------------------------
#define ZA1 (N_NODES * 2)                 // aggr1 (+ x pad, fp32 & fp16)
#define ZA2 (ZA1 + N_NODES * 16)          // aggr2
#define ZDG (ZA2 + N_NODES / 4)           // deg (int4)
#define ZSM (ZDG + N_GRAPHS * 16)         // sums
__global__ void zero_kernel(const float* __restrict__ x) {
    int i = blockIdx.x * blockDim.x + threadIdx.x;
    const float4 z4 = make_float4(0.f, 0.f, 0.f, 0.f);
    if (i < ZA1) {
        reinterpret_cast<float4*>(g_aggr1)[i] = z4;
        int node = i >> 1, h = i & 1;
        int base = node * 7 + h * 4;
        float4 v;
        v.x = __ldg(&x[base + 0]);
        v.y = __ldg(&x[base + 1]);
        v.z = __ldg(&x[base + 2]);
        v.w = (h == 0) ? __ldg(&x[base + 3]) : 0.f;   // j=7 pad
        reinterpret_cast<float4*>(g_x8)[i] = v;
        __half2 p0 = __floats2half2_rn(v.x, v.y);
        __half2 p1 = __floats2half2_rn(v.z, v.w);
        uint2 u;
        u.x = *reinterpret_cast<unsigned*>(&p0);
        u.y = *reinterpret_cast<unsigned*>(&p1);
        *reinterpret_cast<uint2*>(reinterpret_cast<char*>(g_x8h) + node * 16 + h * 8) = u;
    } else if (i < ZA2) {
        reinterpret_cast<float4*>(g_aggr2)[i - ZA1] = z4;
    } else if (i < ZDG) {
        reinterpret_cast<int4*>(g_deg)[i - ZA2] = make_int4(0, 0, 0, 0);
    } else if (i < ZSM) {
        reinterpret_cast<float4*>(g_sums)[i - ZDG] = z4;
    }
    if (i < N_GRAPHS) g_cnt[i] = 0.f;
}

// ---------------- binning 1: histogram of dst (fire-and-forget) --------------
__global__ void hist_kernel(const int* __restrict__ ei) {
    int e = blockIdx.x * blockDim.x + threadIdx.x;
    if (e >= N_EDGES) return;
    atomicAdd(&g_deg[__ldg(&ei[N_EDGES + e])], 1);
}

// ---------------- binning 2: exclusive scan (one block, ILP loads) -----------
#define SCAN_T 1024
#define CHUNK  ((N_NODES + SCAN_T - 1) / SCAN_T)   // 49
__global__ void scan_kernel() {
    __shared__ int ssum[SCAN_T];
    int t = threadIdx.x;
    int beg = t * CHUNK;
    int end = min(beg + CHUNK, N_NODES);
    int s = 0;
    for (int i = beg; i < end; i++) s += __ldg(&g_deg[i]);
    ssum[t] = s;
    __syncthreads();
    for (int d = 1; d < SCAN_T; d <<= 1) {
        int v = (t >= d) ? ssum[t - d] : 0;
        __syncthreads();
        ssum[t] += v;
        __syncthreads();
    }
    int run = (t > 0) ? ssum[t - 1] : 0;
    for (int i = beg; i < end; i++) {
        int dg = g_deg[i];
        g_off[i] = run;
        g_cur[i] = run;
        run += dg;
    }
    if (t == 0) g_off[N_NODES] = N_EDGES;
}

// ---------------- binning 3: scatter records, 4 edges/thread (MLP) -----------
__global__ void scatter_kernel(const int* __restrict__ ei) {
    int t = blockIdx.x * blockDim.x + threadIdx.x;
    if (t >= N_EDGES / 4) return;
    int4 s = __ldg(reinterpret_cast<const int4*>(ei) + t);
    int4 d = __ldg(reinterpret_cast<const int4*>(ei + N_EDGES) + t);
    int e0 = t * 4;
    int p0 = atomicAdd(&g_cur[d.x], 1);
    int p1 = atomicAdd(&g_cur[d.y], 1);
    int p2 = atomicAdd(&g_cur[d.z], 1);
    int p3 = atomicAdd(&g_cur[d.w], 1);
    g_erec[p0] = make_int4(s.x, e0 + 0, d.x, 0);
    g_erec[p1] = make_int4(s.y, e0 + 1, d.y, 0);
    g_erec[p2] = make_int4(s.z, e0 + 2, d.z, 0);
    g_erec[p3] = make_int4(s.w, e0 + 3, d.w, 0);
}

// ---------------- layer 1 edge pass (d = 7), grid-stride, fp16 x gather -----
__global__ void edge1_kernel(const float* __restrict__ ea,
                             const int*   __restrict__ ei,
                             const float* __restrict__ We1,
                             const float* __restrict__ be1) {
    float w[4][7], b[7];
#pragma unroll
    for (int i = 0; i < 4; i++)
#pragma unroll
        for (int j = 0; j < 7; j++)
            w[i][j] = __ldg(&We1[i * 7 + j]);
#pragma unroll
    for (int j = 0; j < 7; j++) b[j] = __ldg(&be1[j]);

    int t  = blockIdx.x * blockDim.x + threadIdx.x;
    int nt = gridDim.x * blockDim.x;
    for (int e = t; e < N_EDGES; e += nt) {
        int src = __ldg(&ei[e]);
        int dst = __ldg(&ei[N_EDGES + e]);
        float4 a  = __ldg(reinterpret_cast<const float4*>(ea) + e);
        uint4 xh = __ldg(reinterpret_cast<const uint4*>(g_x8h) + src);
        float2 x01 = __half22float2(*reinterpret_cast<__half2*>(&xh.x));
        float2 x23 = __half22float2(*reinterpret_cast<__half2*>(&xh.y));
        float2 x45 = __half22float2(*reinterpret_cast<__half2*>(&xh.z));
        float2 x67 = __half22float2(*reinterpret_cast<__half2*>(&xh.w));
        float xs[8] = {x01.x, x01.y, x23.x, x23.y, x45.x, x45.y, x67.x, 0.f};
        float v[8];
#pragma unroll
        for (int j = 0; j < 7; j++) {
            float m = b[j] + a.x * w[0][j] + a.y * w[1][j]
                            + a.z * w[2][j] + a.w * w[3][j];
            v[j] = fmaxf(m + xs[j], 0.f);
        }
        v[7] = 0.f;
        float* p = g_aggr1 + dst * 8;
        asm volatile("red.global.add.v4.f32 [%0], {%1, %2, %3, %4};"
                     :: "l"(p), "f"(v[0]), "f"(v[1]), "f"(v[2]), "f"(v[3]) : "memory");
        asm volatile("red.global.add.v4.f32 [%0], {%1, %2, %3, %4};"
                     :: "l"(p + 4), "f"(v[4]), "f"(v[5]), "f"(v[6]), "f"(v[7]) : "memory");
    }
}

// ---------------- layer 1 node MLP: 7 -> 64 -> 64, 4-node blocked ----------
#define N_GROUPS (N_NODES / 4)
__global__ void node1_kernel(const float* __restrict__ W1a,
                             const float* __restrict__ b1a,
                             const float* __restrict__ W1b,
                             const float* __restrict__ b1b) {
    __shared__ float2 sWa[7 * 32];
    __shared__ float2 sWb[64 * 32];
    __shared__ float  sba[64];
    __shared__ float  sbb[64];
    for (int i = threadIdx.x; i < 7 * 32; i += blockDim.x)
        sWa[i] = reinterpret_cast<const float2*>(W1a)[i];
    for (int i = threadIdx.x; i < 64 * 32; i += blockDim.x)
        sWb[i] = reinterpret_cast<const float2*>(W1b)[i];
    if (threadIdx.x < 64) { sba[threadIdx.x] = b1a[threadIdx.x]; sbb[threadIdx.x] = b1b[threadIdx.x]; }
    __syncthreads();

    int warp = (blockIdx.x * blockDim.x + threadIdx.x) >> 5;
    int nw   = (gridDim.x * blockDim.x) >> 5;
    int lane = threadIdx.x & 31;
    int j    = lane * 2;

    for (int grp = warp; grp < N_GROUPS; grp += nw) {
        int n0 = grp * 4;
        float z[4][7];
#pragma unroll
        for (int m = 0; m < 4; m++)
#pragma unroll
            for (int k = 0; k < 7; k++)
                z[m][k] = g_x8[(n0 + m) * 8 + k] + g_aggr1[(n0 + m) * 8 + k];

        float t0[4], t1[4];
#pragma unroll
        for (int m = 0; m < 4; m++) { t0[m] = sba[j]; t1[m] = sba[j + 1]; }
#pragma unroll
        for (int k = 0; k < 7; k++) {
            float2 w = sWa[k * 32 + lane];
#pragma unroll
            for (int m = 0; m < 4; m++) {
                t0[m] += z[m][k] * w.x;
                t1[m] += z[m][k] * w.y;
            }
        }
#pragma unroll
        for (int m = 0; m < 4; m++) { t0[m] = fmaxf(t0[m], 0.f); t1[m] = fmaxf(t1[m], 0.f); }

        float a0[4], a1[4];
#pragma unroll
        for (int m = 0; m < 4; m++) { a0[m] = sbb[j]; a1[m] = sbb[j + 1]; }
#pragma unroll
        for (int k = 0; k < 64; k++) {
            float2 w = sWb[k * 32 + lane];
#pragma unroll
            for (int m = 0; m < 4; m++) {
                float tk = __shfl_sync(0xffffffffu, (k & 1) ? t1[m] : t0[m], k >> 1);
                a0[m] += tk * w.x;
                a1[m] += tk * w.y;
            }
        }
#pragma unroll
        for (int m = 0; m < 4; m++) {
            float v0 = fmaxf(a0[m], 0.f);   // outer relu from reference
            float v1 = fmaxf(a1[m], 0.f);
            *reinterpret_cast<float2*>(g_h1 + (n0 + m) * 64 + j) = make_float2(v0, v1);
            *reinterpret_cast<__half2*>(g_h1h + (n0 + m) * 64 + j) =
                __floats2half2_rn(v0, v1);
        }
    }
}

// ---------------- layer 2 edge pass: FLAT over dst-sorted edges --------------
// half-warp owns 16 consecutive sorted edges; register accumulate while dst
// unchanged; REDG.v4 only on dst change (~1.5 per chunk). Depth-2 prefetch.
#define E2_CHUNK 16
__global__ void __launch_bounds__(256)
edge2_kernel(const float* __restrict__ ea,
             const float* __restrict__ We2,
             const float* __restrict__ be2) {
    int l    = threadIdx.x & 15;                       // output slice 4l..4l+3
    int hw   = (blockIdx.x * blockDim.x + threadIdx.x) >> 4;
    int base = hw * E2_CHUNK;

    float4 t0 = __ldg(reinterpret_cast<const float4*>(We2 + 0 * 64) + l);
    float4 t1 = __ldg(reinterpret_cast<const float4*>(We2 + 1 * 64) + l);
    float4 t2 = __ldg(reinterpret_cast<const float4*>(We2 + 2 * 64) + l);
    float4 t3 = __ldg(reinterpret_cast<const float4*>(We2 + 3 * 64) + l);
    float4 bb = __ldg(reinterpret_cast<const float4*>(be2) + l);

    // pipeline prologue
    int4 r0 = __ldg(&g_erec[base]);
    int4 r1 = __ldg(&g_erec[base + 1]);
    uint2 h0 = __ldg(reinterpret_cast<const uint2*>(g_h1h + r0.x * 64) + l);
    float4 a0 = __ldg(reinterpret_cast<const float4*>(ea) + r0.y);

    int cur = r0.z;
    float4 acc = make_float4(0.f, 0.f, 0.f, 0.f);

    int4  r2 = r1;
    uint2 hn = h0;
    float4 an = a0;

#pragma unroll
    for (int i = 0; i < E2_CHUNK; i++) {
        if (i + 2 < E2_CHUNK) r2 = __ldg(&g_erec[base + i + 2]);
        if (i + 1 < E2_CHUNK) {
            hn = __ldg(reinterpret_cast<const uint2*>(g_h1h + r1.x * 64) + l);
            an = __ldg(reinterpret_cast<const float4*>(ea) + r1.y);
        }
        if (r0.z != cur) {   // dst changed: flush accumulator
            float* p = g_aggr2 + cur * 64 + l * 4;
            asm volatile("red.global.add.v4.f32 [%0], {%1, %2, %3, %4};"
                         :: "l"(p), "f"(acc.x), "f"(acc.y), "f"(acc.z), "f"(acc.w) : "memory");
            acc = make_float4(0.f, 0.f, 0.f, 0.f);
            cur = r0.z;
        }
        float2 hh0 = __half22float2(*reinterpret_cast<__half2*>(&h0.x));
        float2 hh1 = __half22float2(*reinterpret_cast<__half2*>(&h0.y));
        acc.x += fmaxf(bb.x + a0.x*t0.x + a0.y*t1.x + a0.z*t2.x + a0.w*t3.x + hh0.x, 0.f);
        acc.y += fmaxf(bb.y + a0.x*t0.y + a0.y*t1.y + a0.z*t2.y + a0.w*t3.y + hh0.y, 0.f);
        acc.z += fmaxf(bb.z + a0.x*t0.z + a0.y*t1.z + a0.z*t2.z + a0.w*t3.z + hh1.x, 0.f);
        acc.w += fmaxf(bb.w + a0.x*t0.w + a0.y*t1.w + a0.z*t2.w + a0.w*t3.w + hh1.y, 0.f);
        r0 = r1; r1 = r2; h0 = hn; a0 = an;
    }
    float* p = g_aggr2 + cur * 64 + l * 4;
    asm volatile("red.global.add.v4.f32 [%0], {%1, %2, %3, %4};"
                 :: "l"(p), "f"(acc.x), "f"(acc.y), "f"(acc.z), "f"(acc.w) : "memory");
}

// ---------------- layer 2 node MLP (64->64->64) + pool, 4-node blocked -----
__global__ void node2pool_kernel(const int*   __restrict__ batch,
                                 const float* __restrict__ W2a,
                                 const float* __restrict__ b2a,
                                 const float* __restrict__ W2b,
                                 const float* __restrict__ b2b) {
    __shared__ float2 sWa[64 * 32];
    __shared__ float2 sWb[64 * 32];
    __shared__ float  sba[64];
    __shared__ float  sbb[64];
    for (int i = threadIdx.x; i < 64 * 32; i += blockDim.x) {
        sWa[i] = reinterpret_cast<const float2*>(W2a)[i];
        sWb[i] = reinterpret_cast<const float2*>(W2b)[i];
    }
    if (threadIdx.x < 64) { sba[threadIdx.x] = b2a[threadIdx.x]; sbb[threadIdx.x] = b2b[threadIdx.x]; }
    __syncthreads();

    int warp = (blockIdx.x * blockDim.x + threadIdx.x) >> 5;
    int nw   = (gridDim.x * blockDim.x) >> 5;
    int lane = threadIdx.x & 31;
    int j    = lane * 2;

    for (int grp = warp; grp < N_GROUPS; grp += nw) {
        int n0 = grp * 4;
        float z0[4], z1[4];
#pragma unroll
        for (int m = 0; m < 4; m++) {
            float2 hv = *reinterpret_cast<const float2*>(g_h1 + (n0 + m) * 64 + j);
            float2 av = *reinterpret_cast<const float2*>(g_aggr2 + (n0 + m) * 64 + j);
            z0[m] = hv.x + av.x;
            z1[m] = hv.y + av.y;
        }

        float t0[4], t1[4];
#pragma unroll
        for (int m = 0; m < 4; m++) { t0[m] = sba[j]; t1[m] = sba[j + 1]; }
#pragma unroll
        for (int k = 0; k < 64; k++) {
            float2 w = sWa[k * 32 + lane];
#pragma unroll
            for (int m = 0; m < 4; m++) {
                float zk = __shfl_sync(0xffffffffu, (k & 1) ? z1[m] : z0[m], k >> 1);
                t0[m] += zk * w.x;
                t1[m] += zk * w.y;
            }
        }
#pragma unroll
        for (int m = 0; m < 4; m++) { t0[m] = fmaxf(t0[m], 0.f); t1[m] = fmaxf(t1[m], 0.f); }

        float a0[4], a1[4];
#pragma unroll
        for (int m = 0; m < 4; m++) { a0[m] = sbb[j]; a1[m] = sbb[j + 1]; }
#pragma unroll
        for (int k = 0; k < 64; k++) {
            float2 w = sWb[k * 32 + lane];
#pragma unroll
            for (int m = 0; m < 4; m++) {
                float tk = __shfl_sync(0xffffffffu, (k & 1) ? t1[m] : t0[m], k >> 1);
                a0[m] += tk * w.x;
                a1[m] += tk * w.y;
            }
        }
#pragma unroll
        for (int m = 0; m < 4; m++) {
            float v0 = fmaxf(a0[m], 0.f);   // outer relu from reference
            float v1 = fmaxf(a1[m], 0.f);
            int g = batch[n0 + m];
            float* p = g_sums + g * 64 + j;
            asm volatile("red.global.add.v2.f32 [%0], {%1, %2};"
                         :: "l"(p), "f"(v0), "f"(v1) : "memory");
            if (lane == 0) atomicAdd(&g_cnt[g], 1.0f);
        }
    }
}

// ---------------- final FC: pooled[G,64] @ Wfc[64,12] + bfc -----------------
__global__ void fc_kernel(const float* __restrict__ Wfc,
                          const float* __restrict__ bfc,
                          float* __restrict__ out) {
    int i = blockIdx.x * blockDim.x + threadIdx.x;
    if (i >= N_GRAPHS * 12) return;
    int g = i / 12;
    int c = i % 12;
    float inv = 1.0f / fmaxf(g_cnt[g], 1.0f);
    float acc = 0.f;
#pragma unroll
    for (int k = 0; k < 64; k++)
        acc += g_sums[g * 64 + k] * Wfc[k * 12 + c];
    out[i] = bfc[c] + inv * acc;
}

// ---------------- launch ----------------------------------------------------
extern "C" void kernel_launch(void* const* d_in, const int* in_sizes, int n_in,
                              void* d_out, int out_size) {
    const float* x    = (const float*)d_in[0];
    const float* ea   = (const float*)d_in[1];
    const int*   ei   = (const int*)  d_in[2];
    const int*   batch= (const int*)  d_in[3];
    const float* We1  = (const float*)d_in[4];
    const float* be1  = (const float*)d_in[5];
    const float* W1a  = (const float*)d_in[6];
    const float* b1a  = (const float*)d_in[7];
    const float* W1b  = (const float*)d_in[8];
    const float* b1b  = (const float*)d_in[9];
    const float* We2  = (const float*)d_in[10];
    const float* be2  = (const float*)d_in[11];
    const float* W2a  = (const float*)d_in[12];
    const float* b2a  = (const float*)d_in[13];
    const float* W2b  = (const float*)d_in[14];
    const float* b2b  = (const float*)d_in[15];
    const float* Wfc  = (const float*)d_in[16];
    const float* bfc  = (const float*)d_in[17];
    float* out = (float*)d_out;

    zero_kernel<<<(ZSM + 255) / 256, 256>>>(x);
    hist_kernel<<<(N_EDGES + 255) / 256, 256>>>(ei);
    scan_kernel<<<1, SCAN_T>>>();
    scatter_kernel<<<(N_EDGES / 4 + 255) / 256, 256>>>(ei);
    edge1_kernel<<<1184, 256>>>(ea, ei, We1, be1);
    node1_kernel<<<592, 256>>>(W1a, b1a, W1b, b1b);
    edge2_kernel<<<(N_EDGES / E2_CHUNK) * 16 / 256, 256>>>(ea, We2, be2);
    node2pool_kernel<<<592, 256>>>(batch, W2a, b2a, W2b, b2b);
    fc_kernel<<<(N_GRAPHS * 12 + 255) / 256, 256>>>(Wfc, bfc, out);
}

// round 10
// speedup vs baseline: 1.9668x; 1.9417x over previous
#include <cuda_runtime.h>
#include <cuda_fp16.h>

#define N_NODES  50000
#define N_EDGES  1600000
#define N_GRAPHS 1000

// ---------------- scratch (device globals; no allocation allowed) ----------
__device__ __align__(16) float  g_x8[N_NODES * 8];      // padded node features (fp32)
__device__ __align__(16) __half g_x8h[N_NODES * 8];     // padded node features (fp16)
__device__ __align__(16) __half g_aggr1h[N_NODES * 8];  // layer1 aggregation (fp16 atomics)
__device__ __align__(16) float  g_h1[N_NODES * 64];     // layer1 output (fp32)
__device__ __align__(16) __half g_h1h[N_NODES * 64];    // layer1 output (fp16 gather copy)
__device__ __align__(16) __half g_aggr2h[N_NODES * 64]; // layer2 aggregation (fp16 atomics)
__device__ __align__(16) float  g_sums[N_GRAPHS * 64];  // pooled sums
__device__ __align__(16) float  g_cnt[N_GRAPHS];        // per-graph node counts

// ---------------- zero scratch + pad x ---------------------------------------
// slot map: [0, ZX): x pad (2 slots/node, also zeroes aggr1h for i<N_NODES)
//           [ZX, ZA2): aggr2h uint4 slots   [ZA2, ZSM): sums float4 slots
#define ZX  (N_NODES * 2)
#define ZA2 (ZX + N_NODES * 8)
#define ZSM (ZA2 + N_GRAPHS * 16)
__global__ void zero_kernel(const float* __restrict__ x) {
    int i = blockIdx.x * blockDim.x + threadIdx.x;
    if (i < ZX) {
        int node = i >> 1, h = i & 1;
        int base = node * 7 + h * 4;
        float4 v;
        v.x = __ldg(&x[base + 0]);
        v.y = __ldg(&x[base + 1]);
        v.z = __ldg(&x[base + 2]);
        v.w = (h == 0) ? __ldg(&x[base + 3]) : 0.f;   // j=7 pad
        reinterpret_cast<float4*>(g_x8)[i] = v;
        __half2 p0 = __floats2half2_rn(v.x, v.y);
        __half2 p1 = __floats2half2_rn(v.z, v.w);
        uint2 u;
        u.x = *reinterpret_cast<unsigned*>(&p0);
        u.y = *reinterpret_cast<unsigned*>(&p1);
        *reinterpret_cast<uint2*>(reinterpret_cast<char*>(g_x8h) + node * 16 + h * 8) = u;
        if (i < N_NODES)
            reinterpret_cast<uint4*>(g_aggr1h)[i] = make_uint4(0, 0, 0, 0);
    } else if (i < ZA2) {
        reinterpret_cast<uint4*>(g_aggr2h)[i - ZX] = make_uint4(0, 0, 0, 0);
    } else if (i < ZSM) {
        reinterpret_cast<float4*>(g_sums)[i - ZA2] = make_float4(0.f, 0.f, 0.f, 0.f);
    }
    if (i < N_GRAPHS) g_cnt[i] = 0.f;
}

// ---------------- layer 1 edge pass (d = 7): ONE v4.f16x2 red per edge ------
__global__ void edge1_kernel(const float* __restrict__ ea,
                             const int*   __restrict__ ei,
                             const float* __restrict__ We1,
                             const float* __restrict__ be1) {
    float w[4][7], b[7];
#pragma unroll
    for (int i = 0; i < 4; i++)
#pragma unroll
        for (int j = 0; j < 7; j++)
            w[i][j] = __ldg(&We1[i * 7 + j]);
#pragma unroll
    for (int j = 0; j < 7; j++) b[j] = __ldg(&be1[j]);

    int t  = blockIdx.x * blockDim.x + threadIdx.x;
    int nt = gridDim.x * blockDim.x;
    for (int e = t; e < N_EDGES; e += nt) {
        int src = __ldg(&ei[e]);
        int dst = __ldg(&ei[N_EDGES + e]);
        float4 a = __ldg(reinterpret_cast<const float4*>(ea) + e);
        uint4 xh = __ldg(reinterpret_cast<const uint4*>(g_x8h) + src);
        float2 x01 = __half22float2(*reinterpret_cast<__half2*>(&xh.x));
        float2 x23 = __half22float2(*reinterpret_cast<__half2*>(&xh.y));
        float2 x45 = __half22float2(*reinterpret_cast<__half2*>(&xh.z));
        float2 x67 = __half22float2(*reinterpret_cast<__half2*>(&xh.w));
        float xs[8] = {x01.x, x01.y, x23.x, x23.y, x45.x, x45.y, x67.x, 0.f};
        float v[8];
#pragma unroll
        for (int j = 0; j < 7; j++) {
            float m = b[j] + a.x * w[0][j] + a.y * w[1][j]
                            + a.z * w[2][j] + a.w * w[3][j];
            v[j] = fmaxf(m + xs[j], 0.f);
        }
        v[7] = 0.f;
        __half2 p0 = __floats2half2_rn(v[0], v[1]);
        __half2 p1 = __floats2half2_rn(v[2], v[3]);
        __half2 p2 = __floats2half2_rn(v[4], v[5]);
        __half2 p3 = __floats2half2_rn(v[6], v[7]);
        __half* p = g_aggr1h + dst * 8;
        asm volatile("red.global.add.noftz.v4.f16x2 [%0], {%1, %2, %3, %4};"
                     :: "l"(p),
                        "r"(*reinterpret_cast<unsigned*>(&p0)),
                        "r"(*reinterpret_cast<unsigned*>(&p1)),
                        "r"(*reinterpret_cast<unsigned*>(&p2)),
                        "r"(*reinterpret_cast<unsigned*>(&p3)) : "memory");
    }
}

// ---------------- layer 1 node MLP: 7 -> 64 -> 64, 4-node blocked ----------
#define N_GROUPS (N_NODES / 4)
__global__ void node1_kernel(const float* __restrict__ W1a,
                             const float* __restrict__ b1a,
                             const float* __restrict__ W1b,
                             const float* __restrict__ b1b) {
    __shared__ float2 sWa[7 * 32];
    __shared__ float2 sWb[64 * 32];
    __shared__ float  sba[64];
    __shared__ float  sbb[64];
    for (int i = threadIdx.x; i < 7 * 32; i += blockDim.x)
        sWa[i] = reinterpret_cast<const float2*>(W1a)[i];
    for (int i = threadIdx.x; i < 64 * 32; i += blockDim.x)
        sWb[i] = reinterpret_cast<const float2*>(W1b)[i];
    if (threadIdx.x < 64) { sba[threadIdx.x] = b1a[threadIdx.x]; sbb[threadIdx.x] = b1b[threadIdx.x]; }
    __syncthreads();

    int warp = (blockIdx.x * blockDim.x + threadIdx.x) >> 5;
    int nw   = (gridDim.x * blockDim.x) >> 5;
    int lane = threadIdx.x & 31;
    int j    = lane * 2;

    for (int grp = warp; grp < N_GROUPS; grp += nw) {
        int n0 = grp * 4;
        float z[4][7];
#pragma unroll
        for (int m = 0; m < 4; m++) {
            uint4 ah = *reinterpret_cast<const uint4*>(g_aggr1h + (n0 + m) * 8);
            float2 a01 = __half22float2(*reinterpret_cast<__half2*>(&ah.x));
            float2 a23 = __half22float2(*reinterpret_cast<__half2*>(&ah.y));
            float2 a45 = __half22float2(*reinterpret_cast<__half2*>(&ah.z));
            float2 a67 = __half22float2(*reinterpret_cast<__half2*>(&ah.w));
            float as[7] = {a01.x, a01.y, a23.x, a23.y, a45.x, a45.y, a67.x};
#pragma unroll
            for (int k = 0; k < 7; k++)
                z[m][k] = g_x8[(n0 + m) * 8 + k] + as[k];
        }

        float t0[4], t1[4];
#pragma unroll
        for (int m = 0; m < 4; m++) { t0[m] = sba[j]; t1[m] = sba[j + 1]; }
#pragma unroll
        for (int k = 0; k < 7; k++) {
            float2 w = sWa[k * 32 + lane];
#pragma unroll
            for (int m = 0; m < 4; m++) {
                t0[m] += z[m][k] * w.x;
                t1[m] += z[m][k] * w.y;
            }
        }
#pragma unroll
        for (int m = 0; m < 4; m++) { t0[m] = fmaxf(t0[m], 0.f); t1[m] = fmaxf(t1[m], 0.f); }

        float a0[4], a1[4];
#pragma unroll
        for (int m = 0; m < 4; m++) { a0[m] = sbb[j]; a1[m] = sbb[j + 1]; }
#pragma unroll
        for (int k = 0; k < 64; k++) {
            float2 w = sWb[k * 32 + lane];
#pragma unroll
            for (int m = 0; m < 4; m++) {
                float tk = __shfl_sync(0xffffffffu, (k & 1) ? t1[m] : t0[m], k >> 1);
                a0[m] += tk * w.x;
                a1[m] += tk * w.y;
            }
        }
#pragma unroll
        for (int m = 0; m < 4; m++) {
            float v0 = fmaxf(a0[m], 0.f);   // outer relu from reference
            float v1 = fmaxf(a1[m], 0.f);
            *reinterpret_cast<float2*>(g_h1 + (n0 + m) * 64 + j) = make_float2(v0, v1);
            *reinterpret_cast<__half2*>(g_h1h + (n0 + m) * 64 + j) =
                __floats2half2_rn(v0, v1);
        }
    }
}

// ---------------- layer 2 edge pass (d = 64): 8 lanes per edge --------------
// lane owns output cols 8l..8l+7; weights in regs (loaded once per chunk);
// pair-unrolled; ONE red.v4.f16x2 per lane per edge (8 lane-ops/edge).
#define E2_EPW 8
__global__ void edge2_kernel(const float* __restrict__ ea,
                             const int*   __restrict__ ei,
                             const float* __restrict__ We2,
                             const float* __restrict__ be2) {
    int l    = threadIdx.x & 7;                        // output slice 8l..8l+7
    int grp  = (blockIdx.x * blockDim.x + threadIdx.x) >> 3;
    int base = grp * E2_EPW;

    // per-lane weights: rows 0..3, cols 8l..8l+7 (two float4 per row) + bias
    float4 wa[4], wb[4];
#pragma unroll
    for (int r = 0; r < 4; r++) {
        wa[r] = __ldg(reinterpret_cast<const float4*>(We2 + r * 64) + 2 * l);
        wb[r] = __ldg(reinterpret_cast<const float4*>(We2 + r * 64) + 2 * l + 1);
    }
    float4 ba = __ldg(reinterpret_cast<const float4*>(be2) + 2 * l);
    float4 bc = __ldg(reinterpret_cast<const float4*>(be2) + 2 * l + 1);

#pragma unroll
    for (int i = 0; i < E2_EPW; i += 2) {
        int e0 = base + i;
        int2 s01 = __ldg(reinterpret_cast<const int2*>(ei + e0));
        int2 d01 = __ldg(reinterpret_cast<const int2*>(ei + N_EDGES + e0));
        float4 a0 = __ldg(reinterpret_cast<const float4*>(ea) + e0);
        float4 a1 = __ldg(reinterpret_cast<const float4*>(ea) + e0 + 1);
        uint4 hg0 = __ldg(reinterpret_cast<const uint4*>(g_h1h + s01.x * 64) + l);
        uint4 hg1 = __ldg(reinterpret_cast<const uint4*>(g_h1h + s01.y * 64) + l);

        // edge 0
        {
            float2 h0 = __half22float2(*reinterpret_cast<__half2*>(&hg0.x));
            float2 h1 = __half22float2(*reinterpret_cast<__half2*>(&hg0.y));
            float2 h2 = __half22float2(*reinterpret_cast<__half2*>(&hg0.z));
            float2 h3 = __half22float2(*reinterpret_cast<__half2*>(&hg0.w));
            float m0 = fmaxf(ba.x + a0.x*wa[0].x + a0.y*wa[1].x + a0.z*wa[2].x + a0.w*wa[3].x + h0.x, 0.f);
            float m1 = fmaxf(ba.y + a0.x*wa[0].y + a0.y*wa[1].y + a0.z*wa[2].y + a0.w*wa[3].y + h0.y, 0.f);
            float m2 = fmaxf(ba.z + a0.x*wa[0].z + a0.y*wa[1].z + a0.z*wa[2].z + a0.w*wa[3].z + h1.x, 0.f);
            float m3 = fmaxf(ba.w + a0.x*wa[0].w + a0.y*wa[1].w + a0.z*wa[2].w + a0.w*wa[3].w + h1.y, 0.f);
            float m4 = fmaxf(bc.x + a0.x*wb[0].x + a0.y*wb[1].x + a0.z*wb[2].x + a0.w*wb[3].x + h2.x, 0.f);
            float m5 = fmaxf(bc.y + a0.x*wb[0].y + a0.y*wb[1].y + a0.z*wb[2].y + a0.w*wb[3].y + h2.y, 0.f);
            float m6 = fmaxf(bc.z + a0.x*wb[0].z + a0.y*wb[1].z + a0.z*wb[2].z + a0.w*wb[3].z + h3.x, 0.f);
            float m7 = fmaxf(bc.w + a0.x*wb[0].w + a0.y*wb[1].w + a0.z*wb[2].w + a0.w*wb[3].w + h3.y, 0.f);
            __half2 p0 = __floats2half2_rn(m0, m1);
            __half2 p1 = __floats2half2_rn(m2, m3);
            __half2 p2 = __floats2half2_rn(m4, m5);
            __half2 p3 = __floats2half2_rn(m6, m7);
            __half* p = g_aggr2h + d01.x * 64 + l * 8;
            asm volatile("red.global.add.noftz.v4.f16x2 [%0], {%1, %2, %3, %4};"
                         :: "l"(p),
                            "r"(*reinterpret_cast<unsigned*>(&p0)),
                            "r"(*reinterpret_cast<unsigned*>(&p1)),
                            "r"(*reinterpret_cast<unsigned*>(&p2)),
                            "r"(*reinterpret_cast<unsigned*>(&p3)) : "memory");
        }
        // edge 1
        {
            float2 h0 = __half22float2(*reinterpret_cast<__half2*>(&hg1.x));
            float2 h1 = __half22float2(*reinterpret_cast<__half2*>(&hg1.y));
            float2 h2 = __half22float2(*reinterpret_cast<__half2*>(&hg1.z));
            float2 h3 = __half22float2(*reinterpret_cast<__half2*>(&hg1.w));
            float m0 = fmaxf(ba.x + a1.x*wa[0].x + a1.y*wa[1].x + a1.z*wa[2].x + a1.w*wa[3].x + h0.x, 0.f);
            float m1 = fmaxf(ba.y + a1.x*wa[0].y + a1.y*wa[1].y + a1.z*wa[2].y + a1.w*wa[3].y + h0.y, 0.f);
            float m2 = fmaxf(ba.z + a1.x*wa[0].z + a1.y*wa[1].z + a1.z*wa[2].z + a1.w*wa[3].z + h1.x, 0.f);
            float m3 = fmaxf(ba.w + a1.x*wa[0].w + a1.y*wa[1].w + a1.z*wa[2].w + a1.w*wa[3].w + h1.y, 0.f);
            float m4 = fmaxf(bc.x + a1.x*wb[0].x + a1.y*wb[1].x + a1.z*wb[2].x + a1.w*wb[3].x + h2.x, 0.f);
            float m5 = fmaxf(bc.y + a1.x*wb[0].y + a1.y*wb[1].y + a1.z*wb[2].y + a1.w*wb[3].y + h2.y, 0.f);
            float m6 = fmaxf(bc.z + a1.x*wb[0].z + a1.y*wb[1].z + a1.z*wb[2].z + a1.w*wb[3].z + h3.x, 0.f);
            float m7 = fmaxf(bc.w + a1.x*wb[0].w + a1.y*wb[1].w + a1.z*wb[2].w + a1.w*wb[3].w + h3.y, 0.f);
            __half2 p0 = __floats2half2_rn(m0, m1);
            __half2 p1 = __floats2half2_rn(m2, m3);
            __half2 p2 = __floats2half2_rn(m4, m5);
            __half2 p3 = __floats2half2_rn(m6, m7);
            __half* p = g_aggr2h + d01.y * 64 + l * 8;
            asm volatile("red.global.add.noftz.v4.f16x2 [%0], {%1, %2, %3, %4};"
                         :: "l"(p),
                            "r"(*reinterpret_cast<unsigned*>(&p0)),
                            "r"(*reinterpret_cast<unsigned*>(&p1)),
                            "r"(*reinterpret_cast<unsigned*>(&p2)),
                            "r"(*reinterpret_cast<unsigned*>(&p3)) : "memory");
        }
    }
}

// ---------------- layer 2 node MLP (64->64->64) + pool, 4-node blocked -----
__global__ void node2pool_kernel(const int*   __restrict__ batch,
                                 const float* __restrict__ W2a,
                                 const float* __restrict__ b2a,
                                 const float* __restrict__ W2b,
                                 const float* __restrict__ b2b) {
    __shared__ float2 sWa[64 * 32];
    __shared__ float2 sWb[64 * 32];
    __shared__ float  sba[64];
    __shared__ float  sbb[64];
    for (int i = threadIdx.x; i < 64 * 32; i += blockDim.x) {
        sWa[i] = reinterpret_cast<const float2*>(W2a)[i];
        sWb[i] = reinterpret_cast<const float2*>(W2b)[i];
    }
    if (threadIdx.x < 64) { sba[threadIdx.x] = b2a[threadIdx.x]; sbb[threadIdx.x] = b2b[threadIdx.x]; }
    __syncthreads();

    int warp = (blockIdx.x * blockDim.x + threadIdx.x) >> 5;
    int nw   = (gridDim.x * blockDim.x) >> 5;
    int lane = threadIdx.x & 31;
    int j    = lane * 2;

    for (int grp = warp; grp < N_GROUPS; grp += nw) {
        int n0 = grp * 4;
        float z0[4], z1[4];
#pragma unroll
        for (int m = 0; m < 4; m++) {
            float2 hv = *reinterpret_cast<const float2*>(g_h1 + (n0 + m) * 64 + j);
            float2 av = __half22float2(
                *reinterpret_cast<const __half2*>(g_aggr2h + (n0 + m) * 64 + j));
            z0[m] = hv.x + av.x;
            z1[m] = hv.y + av.y;
        }

        float t0[4], t1[4];
#pragma unroll
        for (int m = 0; m < 4; m++) { t0[m] = sba[j]; t1[m] = sba[j + 1]; }
#pragma unroll
        for (int k = 0; k < 64; k++) {
            float2 w = sWa[k * 32 + lane];
#pragma unroll
            for (int m = 0; m < 4; m++) {
                float zk = __shfl_sync(0xffffffffu, (k & 1) ? z1[m] : z0[m], k >> 1);
                t0[m] += zk * w.x;
                t1[m] += zk * w.y;
            }
        }
#pragma unroll
        for (int m = 0; m < 4; m++) { t0[m] = fmaxf(t0[m], 0.f); t1[m] = fmaxf(t1[m], 0.f); }

        float a0[4], a1[4];
#pragma unroll
        for (int m = 0; m < 4; m++) { a0[m] = sbb[j]; a1[m] = sbb[j + 1]; }
#pragma unroll
        for (int k = 0; k < 64; k++) {
            float2 w = sWb[k * 32 + lane];
#pragma unroll
            for (int m = 0; m < 4; m++) {
                float tk = __shfl_sync(0xffffffffu, (k & 1) ? t1[m] : t0[m], k >> 1);
                a0[m] += tk * w.x;
                a1[m] += tk * w.y;
            }
        }
#pragma unroll
        for (int m = 0; m < 4; m++) {
            float v0 = fmaxf(a0[m], 0.f);   // outer relu from reference
            float v1 = fmaxf(a1[m], 0.f);
            int g = batch[n0 + m];
            float* p = g_sums + g * 64 + j;
            asm volatile("red.global.add.v2.f32 [%0], {%1, %2};"
                         :: "l"(p), "f"(v0), "f"(v1) : "memory");
            if (lane == 0) atomicAdd(&g_cnt[g], 1.0f);
        }
    }
}

// ---------------- final FC: pooled[G,64] @ Wfc[64,12] + bfc -----------------
__global__ void fc_kernel(const float* __restrict__ Wfc,
                          const float* __restrict__ bfc,
                          float* __restrict__ out) {
    int i = blockIdx.x * blockDim.x + threadIdx.x;
    if (i >= N_GRAPHS * 12) return;
    int g = i / 12;
    int c = i % 12;
    float inv = 1.0f / fmaxf(g_cnt[g], 1.0f);
    float acc = 0.f;
#pragma unroll
    for (int k = 0; k < 64; k++)
        acc += g_sums[g * 64 + k] * Wfc[k * 12 + c];
    out[i] = bfc[c] + inv * acc;
}

// ---------------- launch ----------------------------------------------------
extern "C" void kernel_launch(void* const* d_in, const int* in_sizes, int n_in,
                              void* d_out, int out_size) {
    const float* x    = (const float*)d_in[0];
    const float* ea   = (const float*)d_in[1];
    const int*   ei   = (const int*)  d_in[2];
    const int*   batch= (const int*)  d_in[3];
    const float* We1  = (const float*)d_in[4];
    const float* be1  = (const float*)d_in[5];
    const float* W1a  = (const float*)d_in[6];
    const float* b1a  = (const float*)d_in[7];
    const float* W1b  = (const float*)d_in[8];
    const float* b1b  = (const float*)d_in[9];
    const float* We2  = (const float*)d_in[10];
    const float* be2  = (const float*)d_in[11];
    const float* W2a  = (const float*)d_in[12];
    const float* b2a  = (const float*)d_in[13];
    const float* W2b  = (const float*)d_in[14];
    const float* b2b  = (const float*)d_in[15];
    const float* Wfc  = (const float*)d_in[16];
    const float* bfc  = (const float*)d_in[17];
    float* out = (float*)d_out;

    zero_kernel<<<(ZSM + 255) / 256, 256>>>(x);
    edge1_kernel<<<1184, 256>>>(ea, ei, We1, be1);
    node1_kernel<<<592, 256>>>(W1a, b1a, W1b, b1b);
    // 8 lanes/edge, E2_EPW edges per lane-group
    edge2_kernel<<<(N_EDGES / E2_EPW) * 8 / 256, 256>>>(ea, ei, We2, be2);
    node2pool_kernel<<<592, 256>>>(batch, W2a, b2a, W2b, b2b);
    fc_kernel<<<(N_GRAPHS * 12 + 255) / 256, 256>>>(Wfc, bfc, out);
}